// round 2
// baseline (speedup 1.0000x reference)
#include <cuda_runtime.h>
#include <math.h>

#define BB 32
#define SS 64
#define EE 256
#define HH 4
#define DD 64
#define TT (BB*SS)   // 2048 tokens

// ---------------- scratch (device globals — no allocation allowed) ----------
__device__ float g_expW[4][EE*EE];   // exp(Wq), exp(Wk), exp(Wv), exp(Wo)
__device__ float g_ex [TT*EE];       // exp(x - m)
__device__ float g_m  [TT];
__device__ float g_q  [TT*EE];       // RAW Sq = ex @ expWq^T   (no log!)
__device__ float g_k  [TT*EE];       // RAW Sk
__device__ float g_v  [TT*EE];       // full v = m + log(Sv) + bv
__device__ float g_att[TT*EE];
__device__ float g_ex2[TT*EE];
__device__ float g_m2 [TT];

// ---------------- kernel 1: exp of all four weight matrices -----------------
__global__ void expw_kernel(const float* __restrict__ Wq,
                            const float* __restrict__ Wk,
                            const float* __restrict__ Wv,
                            const float* __restrict__ Wo)
{
    int i = blockIdx.x * blockDim.x + threadIdx.x;
    int w = i >> 16;
    int j = i & 0xFFFF;
    const float* src = (w == 0) ? Wq : (w == 1) ? Wk : (w == 2) ? Wv : Wo;
    g_expW[w][j] = __expf(src[j]);
}

// ---------------- kernel 2: per-token row max + exp(x - m) ------------------
__global__ void rowexp_kernel(const float* __restrict__ X,
                              float* __restrict__ ex,
                              float* __restrict__ m)
{
    int t   = blockIdx.x;
    int tid = threadIdx.x;
    float v = X[t * EE + tid];

    __shared__ float red[8];
    float mx = v;
    #pragma unroll
    for (int o = 16; o > 0; o >>= 1)
        mx = fmaxf(mx, __shfl_xor_sync(0xFFFFFFFFu, mx, o));
    if ((tid & 31) == 0) red[tid >> 5] = mx;
    __syncthreads();
    float bm = red[0];
    #pragma unroll
    for (int i = 1; i < 8; ++i) bm = fmaxf(bm, red[i]);

    ex[t * EE + tid] = __expf(v - bm);
    if (tid == 0) m[t] = bm;
}

// ---------------- 128x64 GEMM tile, 8x4 microtile, 256 threads --------------
// S[t,i] = sum_j A[t,j] * W[i,j];  if dolog: Y = m[t] + log(S) + bias[i]
#define GM 128
#define GN 64
#define GK 32

__device__ __forceinline__ void mm128_tile(
    const float* __restrict__ A,
    const float* __restrict__ W,
    const float* __restrict__ bias,
    const float* __restrict__ m,
    float* __restrict__ Y,
    bool dolog)
{
    __shared__ float As[GK][GM + 4];
    __shared__ float Bs[GK][GN + 4];

    const int tid  = threadIdx.x;
    const int tr   = tid >> 4;      // 0..15 -> rows tr*8..+7
    const int tc   = tid & 15;      // 0..15 -> cols tc*4..+3
    const int row0 = blockIdx.y * GM;
    const int col0 = blockIdx.x * GN;

    float acc[8][4];
    #pragma unroll
    for (int r = 0; r < 8; ++r)
        #pragma unroll
        for (int c = 0; c < 4; ++c) acc[r][c] = 0.f;

    for (int k0 = 0; k0 < EE; k0 += GK) {
        // A tile: 128 rows x 32 k, float4 along k. 1024 quads / 256 thr = 4 ea.
        #pragma unroll
        for (int it = 0; it < 4; ++it) {
            int idx = it * 256 + tid;
            int r = idx >> 3, kq = idx & 7;
            float4 t4 = *(const float4*)&A[(row0 + r) * EE + k0 + kq * 4];
            As[kq*4+0][r] = t4.x; As[kq*4+1][r] = t4.y;
            As[kq*4+2][r] = t4.z; As[kq*4+3][r] = t4.w;
        }
        // B tile: 64 rows x 32 k -> 512 quads / 256 thr = 2 ea.
        #pragma unroll
        for (int it = 0; it < 2; ++it) {
            int idx = it * 256 + tid;
            int r = idx >> 3, kq = idx & 7;
            float4 t4 = *(const float4*)&W[(col0 + r) * EE + k0 + kq * 4];
            Bs[kq*4+0][r] = t4.x; Bs[kq*4+1][r] = t4.y;
            Bs[kq*4+2][r] = t4.z; Bs[kq*4+3][r] = t4.w;
        }
        __syncthreads();

        #pragma unroll
        for (int kk = 0; kk < GK; ++kk) {
            float4 a0 = *(const float4*)&As[kk][tr * 8];
            float4 a1 = *(const float4*)&As[kk][tr * 8 + 4];
            float4 b  = *(const float4*)&Bs[kk][tc * 4];
            float av[8] = {a0.x,a0.y,a0.z,a0.w,a1.x,a1.y,a1.z,a1.w};
            #pragma unroll
            for (int r = 0; r < 8; ++r) {
                acc[r][0] += av[r] * b.x;
                acc[r][1] += av[r] * b.y;
                acc[r][2] += av[r] * b.z;
                acc[r][3] += av[r] * b.w;
            }
        }
        __syncthreads();
    }

    if (dolog) {
        float b0 = bias[col0 + tc*4 + 0];
        float b1 = bias[col0 + tc*4 + 1];
        float b2 = bias[col0 + tc*4 + 2];
        float b3 = bias[col0 + tc*4 + 3];
        #pragma unroll
        for (int r = 0; r < 8; ++r) {
            int grow = row0 + tr * 8 + r;
            float mr = m[grow];
            float4 o;
            o.x = mr + __logf(acc[r][0]) + b0;
            o.y = mr + __logf(acc[r][1]) + b1;
            o.z = mr + __logf(acc[r][2]) + b2;
            o.w = mr + __logf(acc[r][3]) + b3;
            *(float4*)&Y[grow * EE + col0 + tc * 4] = o;
        }
    } else {
        #pragma unroll
        for (int r = 0; r < 8; ++r) {
            int grow = row0 + tr * 8 + r;
            float4 o = make_float4(acc[r][0], acc[r][1], acc[r][2], acc[r][3]);
            *(float4*)&Y[grow * EE + col0 + tc * 4] = o;
        }
    }
}

// fused q/k/v: z=0 q (raw), z=1 k (raw), z=2 v (log epilogue)
__global__ __launch_bounds__(256) void lse_matmul_qkv(const float* __restrict__ bv)
{
    int z = blockIdx.z;
    const float* W = g_expW[z];
    float*       Y = (z == 0) ? g_q : (z == 1) ? g_k : g_v;
    mm128_tile(g_ex, W, bv, g_m, Y, z == 2);
}

// ---------------- 64x64 GEMM (4x4 microtile) for the O projection -----------
#define BM 64
#define BN 64
#define BKK 32

__global__ __launch_bounds__(256) void lse_matmul_o(const float* __restrict__ bo,
                                                    float* __restrict__ Y)
{
    __shared__ float As[BKK][BM + 4];
    __shared__ float Bs[BKK][BN + 4];

    const float* __restrict__ A = g_ex2;
    const float* __restrict__ W = g_expW[3];
    const float* __restrict__ m = g_m2;

    const int tid  = threadIdx.x;
    const int tr   = tid >> 4;
    const int tc   = tid & 15;
    const int row0 = blockIdx.y * BM;
    const int col0 = blockIdx.x * BN;

    float acc[4][4];
    #pragma unroll
    for (int r = 0; r < 4; ++r)
        #pragma unroll
        for (int c = 0; c < 4; ++c) acc[r][c] = 0.f;

    for (int k0 = 0; k0 < EE; k0 += BKK) {
        #pragma unroll
        for (int it = 0; it < 2; ++it) {
            int idx = it * 256 + tid;
            int r = idx >> 3, kq = idx & 7;
            float4 a4 = *(const float4*)&A[(row0 + r) * EE + k0 + kq * 4];
            As[kq*4+0][r] = a4.x; As[kq*4+1][r] = a4.y;
            As[kq*4+2][r] = a4.z; As[kq*4+3][r] = a4.w;
            float4 b4 = *(const float4*)&W[(col0 + r) * EE + k0 + kq * 4];
            Bs[kq*4+0][r] = b4.x; Bs[kq*4+1][r] = b4.y;
            Bs[kq*4+2][r] = b4.z; Bs[kq*4+3][r] = b4.w;
        }
        __syncthreads();

        #pragma unroll
        for (int kk = 0; kk < BKK; ++kk) {
            float4 a = *(const float4*)&As[kk][tr * 4];
            float4 b = *(const float4*)&Bs[kk][tc * 4];
            acc[0][0] += a.x * b.x; acc[0][1] += a.x * b.y;
            acc[0][2] += a.x * b.z; acc[0][3] += a.x * b.w;
            acc[1][0] += a.y * b.x; acc[1][1] += a.y * b.y;
            acc[1][2] += a.y * b.z; acc[1][3] += a.y * b.w;
            acc[2][0] += a.z * b.x; acc[2][1] += a.z * b.y;
            acc[2][2] += a.z * b.z; acc[2][3] += a.z * b.w;
            acc[3][0] += a.w * b.x; acc[3][1] += a.w * b.y;
            acc[3][2] += a.w * b.z; acc[3][3] += a.w * b.w;
        }
        __syncthreads();
    }

    float b0 = bo[col0 + tc*4 + 0];
    float b1 = bo[col0 + tc*4 + 1];
    float b2 = bo[col0 + tc*4 + 2];
    float b3 = bo[col0 + tc*4 + 3];
    #pragma unroll
    for (int r = 0; r < 4; ++r) {
        int grow = row0 + tr * 4 + r;
        float mr = m[grow];
        float4 o;
        o.x = mr + __logf(acc[r][0]) + b0;
        o.y = mr + __logf(acc[r][1]) + b1;
        o.z = mr + __logf(acc[r][2]) + b2;
        o.w = mr + __logf(acc[r][3]) + b3;
        *(float4*)&Y[grow * EE + col0 + tc * 4] = o;
    }
}

// ---------------- attention: softmax(q+k) @ v, no log/exp needed -------------
// p[t,hd] = Sq[t,hd]*Sk[t,hd]*exp(bq+bk)[hd]; attn = p / sum_d p (per head)
// out[t, h*64+e] = sum_d attn[t,h,d] * v[(b,d), h*64+e]
// grid: 32 b x 4 token-chunks(16) x 2 head-halves = 256 blocks, 256 threads.
#define ATT_TOK 16

__global__ __launch_bounds__(256) void attention2(const float* __restrict__ bq,
                                                  const float* __restrict__ bk)
{
    __shared__ float v_s[64][128];          // 32 KB
    __shared__ float attn_s[ATT_TOK][128];  //  8 KB

    const int bid = blockIdx.x;
    const int b   = bid >> 3;
    const int s0  = ((bid >> 1) & 3) * ATT_TOK;
    const int hh  = bid & 1;                // which 128-col half of E
    const int tid = threadIdx.x;

    // load v tile: v_s[d][e] = g_v[(b*64+d)*256 + hh*128 + e]
    #pragma unroll
    for (int it = 0; it < 8; ++it) {
        int idx = it * 256 + tid;           // quad index 0..2047
        int d = idx >> 5, eq = idx & 31;
        *(float4*)&v_s[d][eq * 4] =
            *(const float4*)&g_v[(b * 64 + d) * 256 + hh * 128 + eq * 4];
    }

    const int t0   = (tid >> 5) * 2;        // tokens t0, t0+1 (local)
    const int c0   = 4 * (tid & 31);        // cols c0..c0+3 (local, 0..127)
    const int gcol = hh * 128 + c0;
    const int hl   = c0 >> 6;               // local head (0/1)

    float4 wb;
    wb.x = __expf(bq[gcol + 0] + bk[gcol + 0]);
    wb.y = __expf(bq[gcol + 1] + bk[gcol + 1]);
    wb.z = __expf(bq[gcol + 2] + bk[gcol + 2]);
    wb.w = __expf(bq[gcol + 3] + bk[gcol + 3]);

    int rbase = (b * 64 + s0 + t0) * 256 + gcol;
    float4 q0 = *(const float4*)&g_q[rbase];
    float4 k0 = *(const float4*)&g_k[rbase];
    float4 q1 = *(const float4*)&g_q[rbase + 256];
    float4 k1 = *(const float4*)&g_k[rbase + 256];

    float4 p0, p1;
    p0.x = q0.x*k0.x*wb.x; p0.y = q0.y*k0.y*wb.y;
    p0.z = q0.z*k0.z*wb.z; p0.w = q0.w*k0.w*wb.w;
    p1.x = q1.x*k1.x*wb.x; p1.y = q1.y*k1.y*wb.y;
    p1.z = q1.z*k1.z*wb.z; p1.w = q1.w*k1.w*wb.w;

    float s0s = p0.x + p0.y + p0.z + p0.w;
    float s1s = p1.x + p1.y + p1.z + p1.w;
    #pragma unroll
    for (int o = 8; o > 0; o >>= 1) {       // reduce over 16-lane head group
        s0s += __shfl_xor_sync(0xFFFFFFFFu, s0s, o);
        s1s += __shfl_xor_sync(0xFFFFFFFFu, s1s, o);
    }
    float i0 = 1.f / s0s, i1 = 1.f / s1s;
    float4 a0 = make_float4(p0.x*i0, p0.y*i0, p0.z*i0, p0.w*i0);
    float4 a1 = make_float4(p1.x*i1, p1.y*i1, p1.z*i1, p1.w*i1);
    *(float4*)&attn_s[t0    ][c0] = a0;
    *(float4*)&attn_s[t0 + 1][c0] = a1;

    __syncthreads();

    float4 acc0 = make_float4(0.f, 0.f, 0.f, 0.f);
    float4 acc1 = make_float4(0.f, 0.f, 0.f, 0.f);
    #pragma unroll 8
    for (int d = 0; d < 64; ++d) {
        float w0 = attn_s[t0    ][hl * 64 + d];
        float w1 = attn_s[t0 + 1][hl * 64 + d];
        float4 v4 = *(const float4*)&v_s[d][c0];
        acc0.x += w0 * v4.x; acc0.y += w0 * v4.y;
        acc0.z += w0 * v4.z; acc0.w += w0 * v4.w;
        acc1.x += w1 * v4.x; acc1.y += w1 * v4.y;
        acc1.z += w1 * v4.z; acc1.w += w1 * v4.w;
    }

    *(float4*)&g_att[rbase]       = acc0;
    *(float4*)&g_att[rbase + 256] = acc1;
}

// ---------------- launcher ---------------------------------------------------
extern "C" void kernel_launch(void* const* d_in, const int* in_sizes, int n_in,
                              void* d_out, int out_size)
{
    const float* x  = (const float*)d_in[0];
    const float* Wq = (const float*)d_in[1];
    const float* bq = (const float*)d_in[2];
    const float* Wk = (const float*)d_in[3];
    const float* bk = (const float*)d_in[4];
    const float* Wv = (const float*)d_in[5];
    const float* bv = (const float*)d_in[6];
    const float* Wo = (const float*)d_in[7];
    const float* bo = (const float*)d_in[8];
    float* out = (float*)d_out;

    float *g_ex_p, *g_m_p, *g_att_p, *g_ex2_p, *g_m2_p;
    cudaGetSymbolAddress((void**)&g_ex_p,  g_ex);
    cudaGetSymbolAddress((void**)&g_m_p,   g_m);
    cudaGetSymbolAddress((void**)&g_att_p, g_att);
    cudaGetSymbolAddress((void**)&g_ex2_p, g_ex2);
    cudaGetSymbolAddress((void**)&g_m2_p,  g_m2);

    // 1. exp(W) for all four weight matrices
    expw_kernel<<<(4 * EE * EE) / 256, 256>>>(Wq, Wk, Wv, Wo);

    // 2. per-token max + exp(x - m)
    rowexp_kernel<<<TT, 256>>>(x, g_ex_p, g_m_p);

    // 3. Sq, Sk (raw), v (log) — fused, gridDim.z = 3
    {
        dim3 grid(EE / GN, TT / GM, 3);
        lse_matmul_qkv<<<grid, 256>>>(bv);
    }

    // 4. attention
    attention2<<<256, 256>>>(bq, bk);

    // 5. per-token max + exp on attention output
    rowexp_kernel<<<TT, 256>>>(g_att_p, g_ex2_p, g_m2_p);

    // 6. final tropical linear -> d_out
    {
        dim3 grid(EE / BN, TT / BM, 1);
        lse_matmul_o<<<grid, 256>>>(bo, out);
    }
}

// round 3
// speedup vs baseline: 1.4905x; 1.4905x over previous
#include <cuda_runtime.h>
#include <math.h>

#define BB 32
#define SS 64
#define EE 256
#define HH 4
#define DD 64
#define TT (BB*SS)   // 2048 tokens

// ---------------- scratch (device globals — no allocation allowed) ----------
__device__ float g_expW[4][EE*EE];   // exp(Wq), exp(Wk), exp(Wv), exp(Wo)
__device__ float g_ex [TT*EE];       // exp(x - m)
__device__ float g_m  [TT];
__device__ float g_v  [TT*EE];       // v = m + log(Sv) + bv
__device__ float g_att[TT*EE];
__device__ float g_ex2[TT*EE];
__device__ float g_m2 [TT];

// ---------------- K1: exp(W) for all weights  +  rowexp(x) fused ------------
// blocks [0,1024): expw ; blocks [1024, 1024+2048): per-token max+exp
__global__ __launch_bounds__(256) void prep_kernel(
    const float* __restrict__ x,
    const float* __restrict__ Wq, const float* __restrict__ Wk,
    const float* __restrict__ Wv, const float* __restrict__ Wo)
{
    int tid = threadIdx.x;
    if (blockIdx.x < 1024) {
        int i = blockIdx.x * 256 + tid;       // 0 .. 4*65536-1
        int w = i >> 16;
        int j = i & 0xFFFF;
        const float* src = (w == 0) ? Wq : (w == 1) ? Wk : (w == 2) ? Wv : Wo;
        g_expW[w][j] = __expf(src[j]);
    } else {
        int t = blockIdx.x - 1024;
        float v = x[t * EE + tid];

        __shared__ float red[8];
        float mx = v;
        #pragma unroll
        for (int o = 16; o > 0; o >>= 1)
            mx = fmaxf(mx, __shfl_xor_sync(0xFFFFFFFFu, mx, o));
        if ((tid & 31) == 0) red[tid >> 5] = mx;
        __syncthreads();
        float bm = red[0];
        #pragma unroll
        for (int i = 1; i < 8; ++i) bm = fmaxf(bm, red[i]);

        g_ex[t * EE + tid] = __expf(v - bm);
        if (tid == 0) g_m[t] = bm;
    }
}

// ---------------- rowexp for the attention output (K4) ----------------------
__global__ __launch_bounds__(256) void rowexp_kernel(const float* __restrict__ X,
                                                     float* __restrict__ ex,
                                                     float* __restrict__ m)
{
    int t   = blockIdx.x;
    int tid = threadIdx.x;
    float v = X[t * EE + tid];

    __shared__ float red[8];
    float mx = v;
    #pragma unroll
    for (int o = 16; o > 0; o >>= 1)
        mx = fmaxf(mx, __shfl_xor_sync(0xFFFFFFFFu, mx, o));
    if ((tid & 31) == 0) red[tid >> 5] = mx;
    __syncthreads();
    float bm = red[0];
    #pragma unroll
    for (int i = 1; i < 8; ++i) bm = fmaxf(bm, red[i]);

    ex[t * EE + tid] = __expf(v - bm);
    if (tid == 0) m[t] = bm;
}

// ---------------- known-good 64x64 LSE GEMM tile (v and o projections) ------
// Y[t,i] = m[t] + log( sum_j A[t,j] * W[i,j] ) + bias[i]
#define BM 64
#define BN 64
#define BKK 32

__device__ __forceinline__ void lse_mm_tile(
    const float* __restrict__ A,
    const float* __restrict__ W,
    const float* __restrict__ bias,
    const float* __restrict__ m,
    float* __restrict__ Y)
{
    __shared__ float As[BKK][BM + 4];
    __shared__ float Bs[BKK][BN + 4];

    const int tid  = threadIdx.x;
    const int tr   = tid >> 4;      // 0..15
    const int tc   = tid & 15;      // 0..15
    const int row0 = blockIdx.y * BM;
    const int col0 = blockIdx.x * BN;

    float acc[4][4];
    #pragma unroll
    for (int r = 0; r < 4; ++r)
        #pragma unroll
        for (int c = 0; c < 4; ++c) acc[r][c] = 0.f;

    for (int k0 = 0; k0 < EE; k0 += BKK) {
        #pragma unroll
        for (int it = 0; it < 8; ++it) {
            int l = it * 256 + tid;
            int r = l >> 5;          // row in tile (0..63)
            int c = l & 31;          // k within tile
            As[c][r] = A[(row0 + r) * EE + k0 + c];
            Bs[c][r] = W[(col0 + r) * EE + k0 + c];
        }
        __syncthreads();

        #pragma unroll
        for (int kk = 0; kk < BKK; ++kk) {
            float4 a = *(const float4*)&As[kk][tr * 4];
            float4 b = *(const float4*)&Bs[kk][tc * 4];
            acc[0][0] += a.x * b.x; acc[0][1] += a.x * b.y;
            acc[0][2] += a.x * b.z; acc[0][3] += a.x * b.w;
            acc[1][0] += a.y * b.x; acc[1][1] += a.y * b.y;
            acc[1][2] += a.y * b.z; acc[1][3] += a.y * b.w;
            acc[2][0] += a.z * b.x; acc[2][1] += a.z * b.y;
            acc[2][2] += a.z * b.z; acc[2][3] += a.z * b.w;
            acc[3][0] += a.w * b.x; acc[3][1] += a.w * b.y;
            acc[3][2] += a.w * b.z; acc[3][3] += a.w * b.w;
        }
        __syncthreads();
    }

    #pragma unroll
    for (int r = 0; r < 4; ++r) {
        int grow = row0 + tr * 4 + r;
        float mr = m[grow];
        #pragma unroll
        for (int c = 0; c < 4; ++c) {
            int gcol = col0 + tc * 4 + c;
            Y[grow * EE + gcol] = mr + __logf(acc[r][c]) + bias[gcol];
        }
    }
}

__global__ __launch_bounds__(256) void lse_matmul_v(const float* __restrict__ bv)
{
    lse_mm_tile(g_ex, g_expW[2], bv, g_m, g_v);
}

__global__ __launch_bounds__(256) void lse_matmul_o(const float* __restrict__ bo,
                                                    float* __restrict__ Y)
{
    lse_mm_tile(g_ex2, g_expW[3], bo, g_m2, Y);
}

// ---------------- K3: fused dual-GEMM(Sq,Sk) + softmax + attn@v -------------
// One block per (head h, batch b). Rows = tokens b*64..b*64+63,
// cols = head dims h*64..h*64+63 (exactly the softmax axis).
//   Sq = ex @ expWq^T (64x64, K=256), Sk likewise (shared A-tile loads)
//   p  = Sq*Sk*exp(bq+bk); attn = p / rowsum(p)
//   att[t, h*64+e] = sum_d attn[t,d] * v[(b,d), h*64+e]
#define QK_PAD 68   // 64 + 4

__global__ __launch_bounds__(256) void qk_attn_kernel(const float* __restrict__ bq,
                                                      const float* __restrict__ bk)
{
    __shared__ float smem[2 * 64 * QK_PAD];   // 34.8 KB, phase-aliased
    float* As = smem;                 // [32][QK_PAD]
    float* Bq = smem + 32 * QK_PAD;
    float* Bk = smem + 64 * QK_PAD;

    const int h = blockIdx.x;         // 0..3
    const int b = blockIdx.y;         // 0..31
    const int tid = threadIdx.x;
    const int tr = tid >> 4;          // 0..15 (rows tr*4..+3)
    const int tc = tid & 15;          // 0..15 (cols tc*4..+3)

    const float* __restrict__ eWq = g_expW[0];
    const float* __restrict__ eWk = g_expW[1];

    float accq[4][4], acck[4][4];
    #pragma unroll
    for (int r = 0; r < 4; ++r)
        #pragma unroll
        for (int c = 0; c < 4; ++c) { accq[r][c] = 0.f; acck[r][c] = 0.f; }

    const int row_glob = b * 64;      // token base
    const int col_glob = h * 64;      // E-column base

    for (int k0 = 0; k0 < EE; k0 += 32) {
        #pragma unroll
        for (int it = 0; it < 8; ++it) {
            int l = it * 256 + tid;
            int r = l >> 5;           // 0..63
            int c = l & 31;           // k index
            As[c * QK_PAD + r] = g_ex[(row_glob + r) * EE + k0 + c];
            Bq[c * QK_PAD + r] = eWq[(col_glob + r) * EE + k0 + c];
            Bk[c * QK_PAD + r] = eWk[(col_glob + r) * EE + k0 + c];
        }
        __syncthreads();

        #pragma unroll
        for (int kk = 0; kk < 32; ++kk) {
            float4 a  = *(const float4*)&As[kk * QK_PAD + tr * 4];
            float4 q4 = *(const float4*)&Bq[kk * QK_PAD + tc * 4];
            float4 k4 = *(const float4*)&Bk[kk * QK_PAD + tc * 4];
            accq[0][0] += a.x*q4.x; accq[0][1] += a.x*q4.y; accq[0][2] += a.x*q4.z; accq[0][3] += a.x*q4.w;
            accq[1][0] += a.y*q4.x; accq[1][1] += a.y*q4.y; accq[1][2] += a.y*q4.z; accq[1][3] += a.y*q4.w;
            accq[2][0] += a.z*q4.x; accq[2][1] += a.z*q4.y; accq[2][2] += a.z*q4.z; accq[2][3] += a.z*q4.w;
            accq[3][0] += a.w*q4.x; accq[3][1] += a.w*q4.y; accq[3][2] += a.w*q4.z; accq[3][3] += a.w*q4.w;
            acck[0][0] += a.x*k4.x; acck[0][1] += a.x*k4.y; acck[0][2] += a.x*k4.z; acck[0][3] += a.x*k4.w;
            acck[1][0] += a.y*k4.x; acck[1][1] += a.y*k4.y; acck[1][2] += a.y*k4.z; acck[1][3] += a.y*k4.w;
            acck[2][0] += a.z*k4.x; acck[2][1] += a.z*k4.y; acck[2][2] += a.z*k4.z; acck[2][3] += a.z*k4.w;
            acck[3][0] += a.w*k4.x; acck[3][1] += a.w*k4.y; acck[3][2] += a.w*k4.z; acck[3][3] += a.w*k4.w;
        }
        __syncthreads();
    }

    // ---- softmax (2*m_t cancels; p = Sq*Sk*exp(bq+bk)) ----
    float wb[4];
    #pragma unroll
    for (int c = 0; c < 4; ++c) {
        int gc = col_glob + tc * 4 + c;
        wb[c] = __expf(bq[gc] + bk[gc]);
    }

    float p[4][4], rowsum[4];
    #pragma unroll
    for (int r = 0; r < 4; ++r) {
        float s = 0.f;
        #pragma unroll
        for (int c = 0; c < 4; ++c) {
            p[r][c] = accq[r][c] * acck[r][c] * wb[c];
            s += p[r][c];
        }
        // reduce across the 16 threads (tc) sharing this row group
        #pragma unroll
        for (int o = 8; o > 0; o >>= 1)
            s += __shfl_xor_sync(0xFFFFFFFFu, s, o);
        rowsum[r] = s;
    }

    // ---- write attn into smem (aliases As/Bq: safe, all reads done) ----
    float* attn_s = smem;                 // [64][QK_PAD]
    float* v_s    = smem + 64 * QK_PAD;   // [64][QK_PAD]
    #pragma unroll
    for (int r = 0; r < 4; ++r) {
        float inv = 1.f / rowsum[r];
        float4 o4 = make_float4(p[r][0]*inv, p[r][1]*inv, p[r][2]*inv, p[r][3]*inv);
        *(float4*)&attn_s[(tr * 4 + r) * QK_PAD + tc * 4] = o4;
    }

    // ---- load v tile ----
    #pragma unroll
    for (int it = 0; it < 4; ++it) {
        int idx = it * 256 + tid;         // quad 0..1023
        int d = idx >> 4, eq = idx & 15;
        *(float4*)&v_s[d * QK_PAD + eq * 4] =
            *(const float4*)&g_v[(row_glob + d) * EE + col_glob + eq * 4];
    }
    __syncthreads();

    // ---- out = attn @ v (64x64x64) ----
    float4 o0 = make_float4(0,0,0,0), o1 = o0, o2 = o0, o3 = o0;
    #pragma unroll 8
    for (int d = 0; d < 64; ++d) {
        float4 v4 = *(const float4*)&v_s[d * QK_PAD + tc * 4];
        float a0 = attn_s[(tr*4 + 0) * QK_PAD + d];
        float a1 = attn_s[(tr*4 + 1) * QK_PAD + d];
        float a2 = attn_s[(tr*4 + 2) * QK_PAD + d];
        float a3 = attn_s[(tr*4 + 3) * QK_PAD + d];
        o0.x += a0*v4.x; o0.y += a0*v4.y; o0.z += a0*v4.z; o0.w += a0*v4.w;
        o1.x += a1*v4.x; o1.y += a1*v4.y; o1.z += a1*v4.z; o1.w += a1*v4.w;
        o2.x += a2*v4.x; o2.y += a2*v4.y; o2.z += a2*v4.z; o2.w += a2*v4.w;
        o3.x += a3*v4.x; o3.y += a3*v4.y; o3.z += a3*v4.z; o3.w += a3*v4.w;
    }

    int obase = (row_glob + tr * 4) * EE + col_glob + tc * 4;
    *(float4*)&g_att[obase]          = o0;
    *(float4*)&g_att[obase + EE]     = o1;
    *(float4*)&g_att[obase + 2*EE]   = o2;
    *(float4*)&g_att[obase + 3*EE]   = o3;
}

// ---------------- launcher ---------------------------------------------------
extern "C" void kernel_launch(void* const* d_in, const int* in_sizes, int n_in,
                              void* d_out, int out_size)
{
    const float* x  = (const float*)d_in[0];
    const float* Wq = (const float*)d_in[1];
    const float* bq = (const float*)d_in[2];
    const float* Wk = (const float*)d_in[3];
    const float* bk = (const float*)d_in[4];
    const float* Wv = (const float*)d_in[5];
    const float* bv = (const float*)d_in[6];
    const float* Wo = (const float*)d_in[7];
    const float* bo = (const float*)d_in[8];
    float* out = (float*)d_out;

    float *g_att_p, *g_ex2_p, *g_m2_p;
    cudaGetSymbolAddress((void**)&g_att_p, g_att);
    cudaGetSymbolAddress((void**)&g_ex2_p, g_ex2);
    cudaGetSymbolAddress((void**)&g_m2_p,  g_m2);

    // K1: exp(W) + rowexp(x) fused
    prep_kernel<<<1024 + TT, 256>>>(x, Wq, Wk, Wv, Wo);

    // K2: v = m + log(ex @ expWv^T) + bv
    {
        dim3 grid(EE / BN, TT / BM);
        lse_matmul_v<<<grid, 256>>>(bv);
    }

    // K3: fused Sq/Sk GEMM + softmax + attn@v
    {
        dim3 grid(HH, BB);
        qk_attn_kernel<<<grid, 256>>>(bq, bk);
    }

    // K4: rowexp on attention output
    rowexp_kernel<<<TT, 256>>>(g_att_p, g_ex2_p, g_m2_p);

    // K5: final tropical linear -> d_out
    {
        dim3 grid(EE / BN, TT / BM);
        lse_matmul_o<<<grid, 256>>>(bo, out);
    }
}